// round 11
// baseline (speedup 1.0000x reference)
#include <cuda_runtime.h>
#include <math.h>

// Problem constants (fixed by reference setup_inputs)
#define B 32
#define H 64
#define W 64
#define C 256
#define SPATIAL (H * W)                     // 4096
#define NCHUNK 32                           // spatial chunks per batch
#define ROWS_PER_CHUNK (SPATIAL / NCHUNK)   // 128
#define X_ELEMS (B * SPATIAL * C)           // 33554432
#define BN_EPS 1e-3f

// Stage-1 partials (deterministic two-level reduction; no float atomics)
__device__ float g_psum[B][NCHUNK][C];
__device__ float g_pmax[B][NCHUNK][C];

// ---------------------------------------------------------------------------
// Kernel A: per-(batch,chunk) partial sum & max over 128 spatial rows.
// Normal (caching) loads on purpose: the input must stay resident in L2
// so kernel C can re-read it from L2 instead of DRAM.
// ---------------------------------------------------------------------------
__global__ __launch_bounds__(256) void pool_partial_kernel(const float* __restrict__ in)
{
    const int t     = threadIdx.x;
    const int c4    = (t & 63) << 2;     // channel base (multiple of 4)
    const int rg    = t >> 6;            // row group 0..3
    const int chunk = blockIdx.x;
    const int b     = blockIdx.y;

    const float4* p = reinterpret_cast<const float4*>(
        in + ((size_t)(b * SPATIAL + chunk * ROWS_PER_CHUNK + rg)) * C + c4);

    float4 s = make_float4(0.f, 0.f, 0.f, 0.f);
    float4 m = make_float4(-INFINITY, -INFINITY, -INFINITY, -INFINITY);

#pragma unroll
    for (int i = 0; i < ROWS_PER_CHUNK / 4; ++i) {
        const float4 v = p[(size_t)i * C];   // stride 4 rows = C float4
        s.x += v.x; s.y += v.y; s.z += v.z; s.w += v.w;
        m.x = fmaxf(m.x, v.x); m.y = fmaxf(m.y, v.y);
        m.z = fmaxf(m.z, v.z); m.w = fmaxf(m.w, v.w);
    }

    __shared__ float4 sh_s[256];
    __shared__ float4 sh_m[256];
    sh_s[t] = s;
    sh_m[t] = m;
    __syncthreads();

    if (t < 64) {
        float4 S = sh_s[t];
        float4 M = sh_m[t];
#pragma unroll
        for (int g = 1; g < 4; ++g) {
            const float4 s2 = sh_s[t + 64 * g];
            const float4 m2 = sh_m[t + 64 * g];
            S.x += s2.x; S.y += s2.y; S.z += s2.z; S.w += s2.w;
            M.x = fmaxf(M.x, m2.x); M.y = fmaxf(M.y, m2.y);
            M.z = fmaxf(M.z, m2.z); M.w = fmaxf(M.w, m2.w);
        }
        *reinterpret_cast<float4*>(&g_psum[b][chunk][t << 2]) = S;
        *reinterpret_cast<float4*>(&g_pmax[b][chunk][t << 2]) = M;
    }
}

// ---------------------------------------------------------------------------
// Kernel B: one block per batch. Finish pool reduction (fixed order),
// blend avg/max, dense 256x256 + bias, BN, ReLU, per-channel 2-logit
// gumbel-softmax hard gate. Writes gate into the output tail.
// ---------------------------------------------------------------------------
__global__ __launch_bounds__(C) void gate_kernel(
    const float* __restrict__ factor,   // (2,)
    const float* __restrict__ W1,       // (C, C)
    const float* __restrict__ b1,
    const float* __restrict__ gamma,
    const float* __restrict__ beta,
    const float* __restrict__ bn_mean,
    const float* __restrict__ bn_var,
    const float* __restrict__ Wg,       // (C, 2)
    const float* __restrict__ bg,       // (C, 2)
    const float* __restrict__ gumbel,   // (B, C, 2)
    float* __restrict__ gate_out)       // (B, C)
{
    __shared__ float pool_s[C];
    const int b = blockIdx.x;
    const int t = threadIdx.x;

    {
        float s = 0.f;
        float m = -INFINITY;
#pragma unroll
        for (int k = 0; k < NCHUNK; ++k) {
            s += g_psum[b][k][t];
            m = fmaxf(m, g_pmax[b][k][t]);
        }
        const float avg = s * (1.0f / (float)SPATIAL);

        const float a0 = factor[0], a1 = factor[1];
        const float fm = fmaxf(a0, a1);
        const float e0 = expf(a0 - fm), e1 = expf(a1 - fm);
        const float inv = 1.0f / (e0 + e1);
        pool_s[t] = avg * (e0 * inv) + m * (e1 * inv);
    }
    __syncthreads();

    float acc = 0.f;
#pragma unroll 8
    for (int k = 0; k < C; ++k)
        acc = fmaf(pool_s[k], W1[k * C + t], acc);
    float h = acc + b1[t];

    h = gamma[t] * (h - bn_mean[t]) * (1.0f / sqrtf(bn_var[t] + BN_EPS)) + beta[t];
    h = fmaxf(h, 0.f);

    const float l0 = fmaf(h, Wg[t * 2 + 0], bg[t * 2 + 0]);
    const float l1 = fmaf(h, Wg[t * 2 + 1], bg[t * 2 + 1]);
    const float z0 = l0 + gumbel[(b * C + t) * 2 + 0];
    const float z1 = l1 + gumbel[(b * C + t) * 2 + 1];
    const float zm = fmaxf(z0, z1);
    const float q0 = expf(z0 - zm), q1 = expf(z1 - zm);
    const float y1 = q1 / (q0 + q1);
    const float hard1 = (z1 > z0) ? 1.0f : 0.0f;   // jnp.argmax tie -> index 0
    gate_out[b * C + t] = (hard1 - y1) + y1;       // == stop_grad(hard-y)+y
}

// ---------------------------------------------------------------------------
// Kernel C: x = inputs * gate.
//  * block span = 2048 float4 (8192 floats), so the whole block lies in ONE
//    batch and every chunk shares the channel phase -> single gate load.
//  * 8 float4 per thread (warp-coalesced, base + k*256 + tid) for deep MLP.
//  * reversed block order: reads what A cached most recently first.
//  * __stcs output stores: write stream doesn't evict the cached input.
// ---------------------------------------------------------------------------
#define C_F4      (X_ELEMS / 4)          // 8388608 float4
#define C_PER_BLK 2048                   // float4 per block (256 thr * 8)
#define C_BLOCKS  (C_F4 / C_PER_BLK)     // 4096

__global__ __launch_bounds__(256) void apply_gate_kernel(
    const float4* __restrict__ in4,
    const float* __restrict__ gate,      // (B, C)
    float4* __restrict__ out4)
{
    const int blk  = (C_BLOCKS - 1) - blockIdx.x;   // reversed
    const int tid  = threadIdx.x;
    const size_t base = (size_t)blk * C_PER_BLK;

    // whole block is inside one batch; channel phase shared by all 8 chunks
    const int b  = (int)(base >> 18);               // (idx*4) >> 20
    const int c4 = (tid & 63) << 2;
    const float4 g = *reinterpret_cast<const float4*>(&gate[b * C + c4]);

    float4 v[8];
#pragma unroll
    for (int k = 0; k < 8; ++k)
        v[k] = in4[base + (size_t)k * 256 + tid];

#pragma unroll
    for (int k = 0; k < 8; ++k) {
        v[k].x *= g.x; v[k].y *= g.y; v[k].z *= g.z; v[k].w *= g.w;
    }

#pragma unroll
    for (int k = 0; k < 8; ++k)
        __stcs(&out4[base + (size_t)k * 256 + tid], v[k]);
}

extern "C" void kernel_launch(void* const* d_in, const int* in_sizes, int n_in,
                              void* d_out, int out_size)
{
    const float* inputs = (const float*)d_in[0];
    const float* factor = (const float*)d_in[1];
    const float* W1     = (const float*)d_in[2];
    const float* b1     = (const float*)d_in[3];
    const float* gamma  = (const float*)d_in[4];
    const float* beta   = (const float*)d_in[5];
    const float* bnm    = (const float*)d_in[6];
    const float* bnv    = (const float*)d_in[7];
    const float* Wg     = (const float*)d_in[8];
    const float* bg     = (const float*)d_in[9];
    const float* gumbel = (const float*)d_in[10];

    float* out = (float*)d_out;
    float* gate_out = out + X_ELEMS;   // (B, C) broadcast gate lives after x

    dim3 gridA(NCHUNK, B);
    pool_partial_kernel<<<gridA, 256>>>(inputs);

    gate_kernel<<<B, C>>>(factor, W1, b1, gamma, beta, bnm, bnv, Wg, bg,
                          gumbel, gate_out);

    apply_gate_kernel<<<C_BLOCKS, 256>>>(
        (const float4*)inputs, gate_out, (float4*)out);
}